// round 16
// baseline (speedup 1.0000x reference)
#include <cuda_runtime.h>
#include <math.h>
#include <stdint.h>

#define BB 16
#define TT 2048
#define DD 1024
#define CC 6
#define NPART 16    // blocks per batch in fused attention (128 tokens each)
#define NPAIR 4     // pairs per block
#define NPACC (NPART * NPAIR)   // 64 partials per batch
#define QKC 32      // d-chunks in k_qk1 (d-chunk = 32)

// ---------------- device scratch (no allocs allowed) ----------------
__device__ int   g_tok[BB * TT];
__device__ float g_q[BB * DD];
__device__ float g_qk[BB * DD];
__device__ float g_qkp[QKC * BB * DD];      // 2 MB qk partials
__device__ float g_xw[BB * DD];
__device__ float g_tmp[BB * DD];
__device__ float g_tmp2[BB * DD];
__device__ float g_pl[BB * NPACC];
__device__ float g_pacc[BB * NPACC * DD];   // 4 MB pair partial sums

__device__ __forceinline__ float warp_sum(float v) {
#pragma unroll
    for (int o = 16; o > 0; o >>= 1) v += __shfl_down_sync(0xffffffffu, v, o);
    return v;
}
__device__ __forceinline__ float warp_allsum(float v) {
#pragma unroll
    for (int o = 16; o > 0; o >>= 1) v += __shfl_xor_sync(0xffffffffu, v, o);
    return v;
}

// ---------------- K1: q[b] = Wq @ xlast[b] + bq  (grid = D) ------------------
// Also: layout detect + convert 32 tokens/block; zero g_qk and g_xw.
__global__ void k_q(const void* __restrict__ text, const float* __restrict__ emb,
                    const float* __restrict__ Wq, const float* __restrict__ bq, int V) {
    int d = blockIdx.x, t = threadIdx.x;        // 256 threads
    __shared__ int s_ok;
    if (t == 0) s_ok = 1;
    __syncthreads();
    {   // probe first 64 int64-slots (512 B): int64 layout iff all high words 0
        int2 v = ((const int2*)text)[t & 63];
        if (v.y != 0 || v.x < 0 || v.x >= V) s_ok = 0;
    }
    __syncthreads();
    int is64 = s_ok;
    if (t < 32) {   // convert this block's 32 tokens
        int idx = d * 32 + t;
        g_tok[idx] = is64 ? (int)((const long long*)text)[idx]
                          : ((const int*)text)[idx];
    }
    if (d < 64)              g_qk[d * 256 + t] = 0.0f;
    else if (d < 128)        g_xw[(d - 64) * 256 + t] = 0.0f;
    // GEMV row d
    float4 w4 = ((const float4*)(Wq + (size_t)d * DD))[t];
    float acc[BB];
#pragma unroll
    for (int b = 0; b < BB; b++) {
        int li = (b + 1) * TT - 1;
        int row = is64 ? (int)((const long long*)text)[li] : ((const int*)text)[li];
        float4 x = ((const float4*)(emb + (size_t)row * DD))[t];
        acc[b] = w4.x * x.x + w4.y * x.y + w4.z * x.z + w4.w * x.w;
    }
    __shared__ float red[BB][9];
    int lane = t & 31, wid = t >> 5;
#pragma unroll
    for (int b = 0; b < BB; b++) {
        float r = warp_sum(acc[b]);
        if (lane == 0) red[b][wid] = r;
    }
    __syncthreads();
    if (t < BB) {
        float s = 0.f;
#pragma unroll
        for (int w = 0; w < 8; w++) s += red[t][w];
        g_q[t * DD + d] = s + bq[d];
    }
}

// ---------------- K2: qk partials, no atomics (grid (4,QKC), 256 thr) --------
__global__ void k_qk1(const float* __restrict__ Wk) {
    int t = threadIdx.x;
    int j  = blockIdx.x * 256 + t;
    int d0 = blockIdx.y * 32;
    __shared__ float shq[BB * 32];
#pragma unroll
    for (int i = t; i < BB * 32; i += 256) {
        int b = i >> 5, dd = i & 31;
        shq[i] = g_q[b * DD + d0 + dd];
    }
    __syncthreads();
    float w[32];
#pragma unroll
    for (int dd = 0; dd < 32; dd++)
        w[dd] = Wk[(size_t)(d0 + dd) * DD + j];
    float* dst = g_qkp + (size_t)blockIdx.y * BB * DD;
#pragma unroll
    for (int b = 0; b < BB; b++) {
        float a = 0.f;
#pragma unroll
        for (int dd = 0; dd < 32; dd++) a += shq[b * 32 + dd] * w[dd];
        dst[b * DD + j] = a;
    }
}

// ---------------- K3: reduce partials -> g_qk (grid (64,4), atomics) ---------
__global__ void k_qk2() {
    int i = blockIdx.x * 256 + threadIdx.x;     // i in [0, BB*DD)
    int c0 = blockIdx.y * 8;
    float s = 0.f;
#pragma unroll
    for (int c = 0; c < 8; c++) s += g_qkp[(size_t)(c0 + c) * BB * DD + i];
    atomicAdd(&g_qk[i], s);
}

// ---------------- K4: fused single-pass attention, D split across warp pairs ---
// grid (NPART, BB), 256 thr = 8 warps = 4 pairs x 2 D-halves.
// Pair pp: 32 tokens in 8 batches of 4; rows stay in registers across
// dot -> pair-exchange (named barrier) -> no-max exp -> weighted accumulate.
// Epilogue: each warp writes its 512-dim half of the pair partial directly.
__global__ void __launch_bounds__(256, 2) k_attn(const float* __restrict__ emb, float scale) {
    int b = blockIdx.y;
    int t = threadIdx.x, w = t >> 5, lane = t & 31;
    int pp = w >> 1, h = w & 1;
    __shared__ float4 shqk[256];
    __shared__ float  sdots[2][4][2][4];        // [buf][pair][half][jj]
    shqk[t] = ((const float4*)(g_qk + b * DD))[t];
    __syncthreads();
    float4 qv[4];
#pragma unroll
    for (int it = 0; it < 4; it++) qv[it] = shqk[h * 128 + it * 32 + lane];

    int j0 = b * TT + blockIdx.x * 128 + pp * 32;
    float l = 0.f;
    float4 acc[4];
#pragma unroll
    for (int it = 0; it < 4; it++) acc[it] = make_float4(0.f, 0.f, 0.f, 0.f);

    for (int sub = 0; sub < 8; sub++) {
        int rows[4];
#pragma unroll
        for (int jj = 0; jj < 4; jj++) rows[jj] = g_tok[j0 + sub * 4 + jj];
        // load 4 rows (own half) into registers — 16 independent LDG.128
        float4 e[4][4];
#pragma unroll
        for (int jj = 0; jj < 4; jj++) {
            const float4* e4 = (const float4*)(emb + (size_t)rows[jj] * DD) + h * 128;
#pragma unroll
            for (int it = 0; it < 4; it++) e[jj][it] = e4[it * 32 + lane];
        }
        // half-dots
        float dd4[4];
#pragma unroll
        for (int jj = 0; jj < 4; jj++) {
            float d = 0.f;
#pragma unroll
            for (int it = 0; it < 4; it++)
                d += e[jj][it].x * qv[it].x + e[jj][it].y * qv[it].y
                   + e[jj][it].z * qv[it].z + e[jj][it].w * qv[it].w;
            dd4[jj] = d;
        }
#pragma unroll
        for (int jj = 0; jj < 4; jj++) {
            float r = warp_allsum(dd4[jj]);
            if (lane == 0) sdots[sub & 1][pp][h][jj] = r;
        }
        asm volatile("bar.sync %0, 64;" :: "r"(pp + 1) : "memory");
        // weights (pair-uniform, no max, no rescale)
        float pw[4];
#pragma unroll
        for (int jj = 0; jj < 4; jj++) {
            pw[jj] = __expf((sdots[sub & 1][pp][0][jj] + sdots[sub & 1][pp][1][jj]) * scale);
            l += pw[jj];
        }
#pragma unroll
        for (int jj = 0; jj < 4; jj++) {
#pragma unroll
            for (int it = 0; it < 4; it++) {
                acc[it].x += pw[jj] * e[jj][it].x; acc[it].y += pw[jj] * e[jj][it].y;
                acc[it].z += pw[jj] * e[jj][it].z; acc[it].w += pw[jj] * e[jj][it].w;
            }
        }
    }

    // ---- direct per-pair partial write (no block combine, no extra sync) ----
    int pidx = (b * NPART + blockIdx.x) * NPAIR + pp;
    float4* dst = (float4*)(g_pacc + (size_t)pidx * DD);
#pragma unroll
    for (int it = 0; it < 4; it++)
        dst[h * 128 + it * 32 + lane] = acc[it];
    if (h == 0 && lane == 0) g_pl[pidx] = l;    // l is pair-uniform
}

// ---------------- K5: combine partials -> g_xw (grid (8,BB), atomics) --------
__global__ void k_attn2() {
    int b = blockIdx.y, t = threadIdx.x;
    int c0 = blockIdx.x * 8;
    const float4* base = (const float4*)(g_pacc + (size_t)b * NPACC * DD);
    float4 a = make_float4(0.f, 0.f, 0.f, 0.f);
#pragma unroll
    for (int k = 0; k < 8; k++) {
        float4 v = base[(size_t)(c0 + k) * (DD / 4) + t];
        a.x += v.x; a.y += v.y; a.z += v.z; a.w += v.w;
    }
    float* dst = g_xw + b * DD + t * 4;
    atomicAdd(dst + 0, a.x); atomicAdd(dst + 1, a.y);
    atomicAdd(dst + 2, a.z); atomicAdd(dst + 3, a.w);
}

// ---------------- K6: tmp[b] = (Wv @ xw[b]) / L_b + bv + xlast[b]  (grid = D) -----
__global__ void k_v(const float* __restrict__ emb, const float* __restrict__ Wv,
                    const float* __restrict__ bv) {
    int d = blockIdx.x, t = threadIdx.x;
    __shared__ float sLinv[BB];
    if (t < BB) {
        float s = 0.f;
#pragma unroll 8
        for (int c = 0; c < NPACC; c++) s += g_pl[t * NPACC + c];
        sLinv[t] = 1.0f / s;
    }
    float4 w4 = ((const float4*)(Wv + (size_t)d * DD))[t];
    float acc[BB];
#pragma unroll
    for (int b = 0; b < BB; b++) {
        float4 x = ((const float4*)(g_xw + b * DD))[t];
        acc[b] = w4.x * x.x + w4.y * x.y + w4.z * x.z + w4.w * x.w;
    }
    __shared__ float red[BB][9];
    int lane = t & 31, wid = t >> 5;
#pragma unroll
    for (int b = 0; b < BB; b++) {
        float r = warp_sum(acc[b]);
        if (lane == 0) red[b][wid] = r;
    }
    __syncthreads();
    if (t < BB) {
        float s = 0.f;
#pragma unroll
        for (int w = 0; w < 8; w++) s += red[t][w];
        int row = g_tok[(t + 1) * TT - 1];
        g_tmp[t * DD + d] = s * sLinv[t] + bv[d] + emb[(size_t)row * DD + d];
    }
}

// ---------------- K7: tmp2[b] = y + Wfc @ y + bfc, y = tmp[b]/||tmp[b]|| -------
__global__ void k_fc(const float* __restrict__ Wfc, const float* __restrict__ bfc) {
    int d = blockIdx.x, t = threadIdx.x;
    float4 w4 = ((const float4*)(Wfc + (size_t)d * DD))[t];
    float acc[BB], ssq[BB];
#pragma unroll
    for (int b = 0; b < BB; b++) {
        float4 x = ((const float4*)(g_tmp + b * DD))[t];
        acc[b] = w4.x * x.x + w4.y * x.y + w4.z * x.z + w4.w * x.w;
        ssq[b] = x.x * x.x + x.y * x.y + x.z * x.z + x.w * x.w;
    }
    __shared__ float red[BB][9];
    __shared__ float red2[BB][9];
    int lane = t & 31, wid = t >> 5;
#pragma unroll
    for (int b = 0; b < BB; b++) {
        float r = warp_sum(acc[b]);
        float r2 = warp_sum(ssq[b]);
        if (lane == 0) { red[b][wid] = r; red2[b][wid] = r2; }
    }
    __syncthreads();
    if (t < BB) {
        float s = 0.f, ss = 0.f;
#pragma unroll
        for (int w = 0; w < 8; w++) { s += red[t][w]; ss += red2[t][w]; }
        float inv = 1.0f / fmaxf(sqrtf(ss), 1e-12f);
        g_tmp2[t * DD + d] = (g_tmp[t * DD + d] + s) * inv + bfc[d];
    }
}

// ---------------- K8: l2norm + sigmoid(Wo @ z + bo) ----------------
__global__ void k_out(const float* __restrict__ Wo, const float* __restrict__ bo,
                      float* __restrict__ out) {
    int b = blockIdx.x, t = threadIdx.x;
    float4 v = ((const float4*)(g_tmp2 + b * DD))[t];
    float ss = v.x * v.x + v.y * v.y + v.z * v.z + v.w * v.w;
    __shared__ float sh[256];
    __shared__ float inv2;
    sh[t] = ss; __syncthreads();
    for (int s = 128; s > 0; s >>= 1) { if (t < s) sh[t] += sh[t + s]; __syncthreads(); }
    if (t == 0) inv2 = 1.0f / fmaxf(sqrtf(sh[0]), 1e-12f);
    __syncthreads();
    int wid = t >> 5, lane = t & 31;
    if (wid < CC) {
        float a = 0.f;
        for (int k = lane; k < DD; k += 32)
            a += Wo[wid * DD + k] * g_tmp2[b * DD + k];
        a = warp_sum(a);
        if (lane == 0) {
            float logit = a * inv2 + bo[wid];
            out[b * CC + wid] = 1.0f / (1.0f + expf(-logit));
        }
    }
}

// ---------------- launch ----------------
extern "C" void kernel_launch(void* const* d_in, const int* in_sizes, int n_in,
                              void* d_out, int out_size) {
    const void*  text = d_in[0];
    const float* emb  = (const float*)d_in[2];
    const float* Wq   = (const float*)d_in[3];
    const float* bq   = (const float*)d_in[4];
    const float* Wk   = (const float*)d_in[5];
    const float* Wv   = (const float*)d_in[7];
    const float* bv   = (const float*)d_in[8];
    const float* Wfc  = (const float*)d_in[9];
    const float* bfc  = (const float*)d_in[10];
    const float* Wo   = (const float*)d_in[11];
    const float* bo   = (const float*)d_in[12];
    int V = in_sizes[2] / DD;

    k_q<<<DD, 256>>>(text, emb, Wq, bq, V);
    dim3 gq1(4, QKC);
    k_qk1<<<gq1, 256>>>(Wk);
    dim3 gq2(64, 4);
    k_qk2<<<gq2, 256>>>();
    dim3 gat(NPART, BB);
    k_attn<<<gat, 256>>>(emb, 1.0f / 32.0f);
    dim3 ga2(8, BB);
    k_attn2<<<ga2, 256>>>();
    k_v<<<DD, 256>>>(emb, Wv, bv);
    k_fc<<<DD, 256>>>(Wfc, bfc);
    k_out<<<BB, 256>>>(Wo, bo, (float*)d_out);
}

// round 17
// speedup vs baseline: 1.1068x; 1.1068x over previous
#include <cuda_runtime.h>
#include <math.h>
#include <stdint.h>

#define BB 16
#define TT 2048
#define DD 1024
#define CC 6
#define NPART 16    // blocks per batch in fused attention (128 tokens each)
#define QKC 32      // d-chunks in k_qk1 (d-chunk = 32)

// ---------------- device scratch (no allocs allowed) ----------------
__device__ int   g_tok[BB * TT];
__device__ float g_q[BB * DD];
__device__ float g_qk[BB * DD];
__device__ float g_qkp[QKC * BB * DD];      // 2 MB qk partials
__device__ float g_xw[BB * DD];
__device__ float g_l[BB];
__device__ float g_tmp[BB * DD];
__device__ float g_tmp2[BB * DD];

__device__ __forceinline__ float warp_sum(float v) {
#pragma unroll
    for (int o = 16; o > 0; o >>= 1) v += __shfl_down_sync(0xffffffffu, v, o);
    return v;
}
__device__ __forceinline__ float warp_allsum(float v) {
#pragma unroll
    for (int o = 16; o > 0; o >>= 1) v += __shfl_xor_sync(0xffffffffu, v, o);
    return v;
}

// ---------------- K1: q[b] = Wq @ xlast[b] + bq  (grid = D) ------------------
// Also: layout detect + convert 32 tokens/block; zero g_xw and g_l.
__global__ void k_q(const void* __restrict__ text, const float* __restrict__ emb,
                    const float* __restrict__ Wq, const float* __restrict__ bq, int V) {
    int d = blockIdx.x, t = threadIdx.x;        // 256 threads
    __shared__ int s_ok;
    if (t == 0) s_ok = 1;
    __syncthreads();
    {   // probe first 64 int64-slots (512 B): int64 layout iff all high words 0
        int2 v = ((const int2*)text)[t & 63];
        if (v.y != 0 || v.x < 0 || v.x >= V) s_ok = 0;
    }
    __syncthreads();
    int is64 = s_ok;
    if (t < 32) {   // convert this block's 32 tokens
        int idx = d * 32 + t;
        g_tok[idx] = is64 ? (int)((const long long*)text)[idx]
                          : ((const int*)text)[idx];
    }
    if (d < 64) g_xw[d * 256 + t] = 0.0f;
    else if (d == 64 && t < BB) g_l[t] = 0.0f;
    // GEMV row d
    float4 w4 = ((const float4*)(Wq + (size_t)d * DD))[t];
    float acc[BB];
#pragma unroll
    for (int b = 0; b < BB; b++) {
        int li = (b + 1) * TT - 1;
        int row = is64 ? (int)((const long long*)text)[li] : ((const int*)text)[li];
        float4 x = ((const float4*)(emb + (size_t)row * DD))[t];
        acc[b] = w4.x * x.x + w4.y * x.y + w4.z * x.z + w4.w * x.w;
    }
    __shared__ float red[BB][9];
    int lane = t & 31, wid = t >> 5;
#pragma unroll
    for (int b = 0; b < BB; b++) {
        float r = warp_sum(acc[b]);
        if (lane == 0) red[b][wid] = r;
    }
    __syncthreads();
    if (t < BB) {
        float s = 0.f;
#pragma unroll
        for (int w = 0; w < 8; w++) s += red[t][w];
        g_q[t * DD + d] = s + bq[d];
    }
}

// ---------------- K2: qk partials, no atomics (grid (4,QKC), 256 thr) --------
__global__ void k_qk1(const float* __restrict__ Wk) {
    int t = threadIdx.x;
    int j  = blockIdx.x * 256 + t;
    int d0 = blockIdx.y * 32;
    __shared__ float shq[BB * 32];
#pragma unroll
    for (int i = t; i < BB * 32; i += 256) {
        int b = i >> 5, dd = i & 31;
        shq[i] = g_q[b * DD + d0 + dd];
    }
    __syncthreads();
    float w[32];
#pragma unroll
    for (int dd = 0; dd < 32; dd++)
        w[dd] = Wk[(size_t)(d0 + dd) * DD + j];
    float* dst = g_qkp + (size_t)blockIdx.y * BB * DD;
#pragma unroll
    for (int b = 0; b < BB; b++) {
        float a = 0.f;
#pragma unroll
        for (int dd = 0; dd < 32; dd++) a += shq[b * 32 + dd] * w[dd];
        dst[b * DD + j] = a;
    }
}

// ---------------- K3: full reduce partials -> g_qk (grid 64, 256 thr) --------
// 32 independent coalesced loads per thread; no atomics, no pre-zeroing.
__global__ void k_qk2() {
    int i = blockIdx.x * 256 + threadIdx.x;     // i in [0, BB*DD)
    float s = 0.f;
#pragma unroll
    for (int c = 0; c < QKC; c++) s += g_qkp[(size_t)c * BB * DD + i];
    g_qk[i] = s;
}

// ---------------- K4: fused single-pass attention, D split across warp pairs ---
// grid (NPART, BB), 256 thr = 8 warps = 4 pairs x 2 D-halves.
// Pair pp: 32 tokens in 8 batches of 4; rows stay in registers across
// dot -> pair-exchange (named barrier) -> no-max exp -> weighted accumulate.
// Epilogue: atomically accumulate the pair partial straight into g_xw / g_l.
__global__ void __launch_bounds__(256, 2) k_attn(const float* __restrict__ emb, float scale) {
    int b = blockIdx.y;
    int t = threadIdx.x, w = t >> 5, lane = t & 31;
    int pp = w >> 1, h = w & 1;
    __shared__ float4 shqk[256];
    __shared__ float  sdots[2][4][2][4];        // [buf][pair][half][jj]
    shqk[t] = ((const float4*)(g_qk + b * DD))[t];
    __syncthreads();
    float4 qv[4];
#pragma unroll
    for (int it = 0; it < 4; it++) qv[it] = shqk[h * 128 + it * 32 + lane];

    int j0 = b * TT + blockIdx.x * 128 + pp * 32;
    float l = 0.f;
    float4 acc[4];
#pragma unroll
    for (int it = 0; it < 4; it++) acc[it] = make_float4(0.f, 0.f, 0.f, 0.f);

    for (int sub = 0; sub < 8; sub++) {
        int rows[4];
#pragma unroll
        for (int jj = 0; jj < 4; jj++) rows[jj] = g_tok[j0 + sub * 4 + jj];
        // load 4 rows (own half) into registers — 16 independent LDG.128
        float4 e[4][4];
#pragma unroll
        for (int jj = 0; jj < 4; jj++) {
            const float4* e4 = (const float4*)(emb + (size_t)rows[jj] * DD) + h * 128;
#pragma unroll
            for (int it = 0; it < 4; it++) e[jj][it] = e4[it * 32 + lane];
        }
        // half-dots
        float dd4[4];
#pragma unroll
        for (int jj = 0; jj < 4; jj++) {
            float d = 0.f;
#pragma unroll
            for (int it = 0; it < 4; it++)
                d += e[jj][it].x * qv[it].x + e[jj][it].y * qv[it].y
                   + e[jj][it].z * qv[it].z + e[jj][it].w * qv[it].w;
            dd4[jj] = d;
        }
#pragma unroll
        for (int jj = 0; jj < 4; jj++) {
            float r = warp_allsum(dd4[jj]);
            if (lane == 0) sdots[sub & 1][pp][h][jj] = r;
        }
        asm volatile("bar.sync %0, 64;" :: "r"(pp + 1) : "memory");
        // weights (pair-uniform, no max, no rescale)
        float pw[4];
#pragma unroll
        for (int jj = 0; jj < 4; jj++) {
            pw[jj] = __expf((sdots[sub & 1][pp][0][jj] + sdots[sub & 1][pp][1][jj]) * scale);
            l += pw[jj];
        }
#pragma unroll
        for (int jj = 0; jj < 4; jj++) {
#pragma unroll
            for (int it = 0; it < 4; it++) {
                acc[it].x += pw[jj] * e[jj][it].x; acc[it].y += pw[jj] * e[jj][it].y;
                acc[it].z += pw[jj] * e[jj][it].z; acc[it].w += pw[jj] * e[jj][it].w;
            }
        }
    }

    // ---- epilogue: atomic accumulate into g_xw (spread addresses) ----
    float* dst = g_xw + b * DD + h * 512;
#pragma unroll
    for (int it = 0; it < 4; it++) {
        int o = (it * 32 + lane) * 4;
        atomicAdd(dst + o + 0, acc[it].x); atomicAdd(dst + o + 1, acc[it].y);
        atomicAdd(dst + o + 2, acc[it].z); atomicAdd(dst + o + 3, acc[it].w);
    }
    if (h == 0 && lane == 0) atomicAdd(&g_l[b], l);
}

// ---------------- K5: tmp[b] = (Wv @ xw[b]) / L_b + bv + xlast[b]  (grid = D) -----
__global__ void k_v(const float* __restrict__ emb, const float* __restrict__ Wv,
                    const float* __restrict__ bv) {
    int d = blockIdx.x, t = threadIdx.x;
    __shared__ float sLinv[BB];
    if (t < BB) sLinv[t] = 1.0f / g_l[t];
    float4 w4 = ((const float4*)(Wv + (size_t)d * DD))[t];
    float acc[BB];
#pragma unroll
    for (int b = 0; b < BB; b++) {
        float4 x = ((const float4*)(g_xw + b * DD))[t];
        acc[b] = w4.x * x.x + w4.y * x.y + w4.z * x.z + w4.w * x.w;
    }
    __shared__ float red[BB][9];
    int lane = t & 31, wid = t >> 5;
#pragma unroll
    for (int b = 0; b < BB; b++) {
        float r = warp_sum(acc[b]);
        if (lane == 0) red[b][wid] = r;
    }
    __syncthreads();
    if (t < BB) {
        float s = 0.f;
#pragma unroll
        for (int w = 0; w < 8; w++) s += red[t][w];
        int row = g_tok[(t + 1) * TT - 1];
        g_tmp[t * DD + d] = s * sLinv[t] + bv[d] + emb[(size_t)row * DD + d];
    }
}

// ---------------- K6: tmp2[b] = y + Wfc @ y + bfc, y = tmp[b]/||tmp[b]|| -------
__global__ void k_fc(const float* __restrict__ Wfc, const float* __restrict__ bfc) {
    int d = blockIdx.x, t = threadIdx.x;
    float4 w4 = ((const float4*)(Wfc + (size_t)d * DD))[t];
    float acc[BB], ssq[BB];
#pragma unroll
    for (int b = 0; b < BB; b++) {
        float4 x = ((const float4*)(g_tmp + b * DD))[t];
        acc[b] = w4.x * x.x + w4.y * x.y + w4.z * x.z + w4.w * x.w;
        ssq[b] = x.x * x.x + x.y * x.y + x.z * x.z + x.w * x.w;
    }
    __shared__ float red[BB][9];
    __shared__ float red2[BB][9];
    int lane = t & 31, wid = t >> 5;
#pragma unroll
    for (int b = 0; b < BB; b++) {
        float r = warp_sum(acc[b]);
        float r2 = warp_sum(ssq[b]);
        if (lane == 0) { red[b][wid] = r; red2[b][wid] = r2; }
    }
    __syncthreads();
    if (t < BB) {
        float s = 0.f, ss = 0.f;
#pragma unroll
        for (int w = 0; w < 8; w++) { s += red[t][w]; ss += red2[t][w]; }
        float inv = 1.0f / fmaxf(sqrtf(ss), 1e-12f);
        g_tmp2[t * DD + d] = (g_tmp[t * DD + d] + s) * inv + bfc[d];
    }
}

// ---------------- K7: l2norm + sigmoid(Wo @ z + bo) ----------------
__global__ void k_out(const float* __restrict__ Wo, const float* __restrict__ bo,
                      float* __restrict__ out) {
    int b = blockIdx.x, t = threadIdx.x;
    float4 v = ((const float4*)(g_tmp2 + b * DD))[t];
    float ss = v.x * v.x + v.y * v.y + v.z * v.z + v.w * v.w;
    __shared__ float sh[256];
    __shared__ float inv2;
    sh[t] = ss; __syncthreads();
    for (int s = 128; s > 0; s >>= 1) { if (t < s) sh[t] += sh[t + s]; __syncthreads(); }
    if (t == 0) inv2 = 1.0f / fmaxf(sqrtf(sh[0]), 1e-12f);
    __syncthreads();
    int wid = t >> 5, lane = t & 31;
    if (wid < CC) {
        float a = 0.f;
        for (int k = lane; k < DD; k += 32)
            a += Wo[wid * DD + k] * g_tmp2[b * DD + k];
        a = warp_sum(a);
        if (lane == 0) {
            float logit = a * inv2 + bo[wid];
            out[b * CC + wid] = 1.0f / (1.0f + expf(-logit));
        }
    }
}

// ---------------- launch ----------------
extern "C" void kernel_launch(void* const* d_in, const int* in_sizes, int n_in,
                              void* d_out, int out_size) {
    const void*  text = d_in[0];
    const float* emb  = (const float*)d_in[2];
    const float* Wq   = (const float*)d_in[3];
    const float* bq   = (const float*)d_in[4];
    const float* Wk   = (const float*)d_in[5];
    const float* Wv   = (const float*)d_in[7];
    const float* bv   = (const float*)d_in[8];
    const float* Wfc  = (const float*)d_in[9];
    const float* bfc  = (const float*)d_in[10];
    const float* Wo   = (const float*)d_in[11];
    const float* bo   = (const float*)d_in[12];
    int V = in_sizes[2] / DD;

    k_q<<<DD, 256>>>(text, emb, Wq, bq, V);
    dim3 gq1(4, QKC);
    k_qk1<<<gq1, 256>>>(Wk);
    k_qk2<<<64, 256>>>();
    dim3 gat(NPART, BB);
    k_attn<<<gat, 256>>>(emb, 1.0f / 32.0f);
    k_v<<<DD, 256>>>(emb, Wv, bv);
    k_fc<<<DD, 256>>>(Wfc, bfc);
    k_out<<<BB, 256>>>(Wo, bo, (float*)d_out);
}